// round 14
// baseline (speedup 1.0000x reference)
#include <cuda_runtime.h>
#include <math.h>

#define Nn   10000
#define Tt   12
#define Ee   100000
#define NTc  (Nn*Tt)        // 120000
#define NTDc (NTc*64)       // 7680000
#define SCAT_BLKS 782       // ceil(2*Ee/256)
#define ELLCAP 64

typedef unsigned long long ull;

// ---------------- scratch ----------------
__device__ float g_h[NTDc];          // BN2 output (input to FFN)
__device__ float g_z[2][NTDc];       // per-relation projected features
__device__ float g_x2[NTDc];         // residual x + m1 + m2
__device__ float g_el[2][NTc*4];
__device__ float g_er[2][NTc*4];
__device__ int   g_slot[2][Nn];      // per-node edge counters (gat resets)
__device__ int   g_ell[2][Nn*ELLCAP]; // src byte offsets (src*3072), ELL rows

// ---------------- f32x2 helpers ----------------
__device__ __forceinline__ ull pk(float a, float b){
    ull r;
    asm("mov.b64 %0, {%1, %2};" : "=l"(r) : "r"(__float_as_uint(a)), "r"(__float_as_uint(b)));
    return r;
}
__device__ __forceinline__ ull fma2(ull a, ull b, ull c){
    ull d;
    asm("fma.rn.f32x2 %0, %1, %2, %3;" : "=l"(d) : "l"(a), "l"(b), "l"(c));
    return d;
}
__device__ __forceinline__ ull mul2(ull a, ull b){
    ull d;
    asm("mul.rn.f32x2 %0, %1, %2;" : "=l"(d) : "l"(a), "l"(b));
    return d;
}
__device__ __forceinline__ ull add2(ull a, ull b){
    ull d;
    asm("add.rn.f32x2 %0, %1, %2;" : "=l"(d) : "l"(a), "l"(b));
    return d;
}
__device__ __forceinline__ float2 upk(ull v){
    unsigned lo, hi;
    asm("mov.b64 {%0, %1}, %2;" : "=r"(lo), "=r"(hi) : "l"(v));
    return make_float2(__uint_as_float(lo), __uint_as_float(hi));
}
__device__ __forceinline__ float rmax32(float v){
    #pragma unroll
    for (int o = 16; o; o >>= 1)
        v = fmaxf(v, __shfl_xor_sync(0xffffffffu, v, o));
    return v;
}
__device__ __forceinline__ float radd32(float v){
    #pragma unroll
    for (int o = 16; o; o >>= 1)
        v += __shfl_xor_sync(0xffffffffu, v, o);
    return v;
}
__device__ __forceinline__ float lrelu(float a){
    return (a > 0.f) ? a : 0.2f*a;
}

// ---------------- fused: ELL scatter (blocks 0..781) + BN1/z/el/er (rest) -----
// BN1 folded: z = sc_node*(x@W) + shift_node*colsum(W).
__global__ void __launch_bounds__(256, 4)
scatter_zel(const int* __restrict__ src1, const int* __restrict__ dst1,
            const int* __restrict__ src2, const int* __restrict__ dst2,
            const float* __restrict__ x,
            const float* __restrict__ bg, const float* __restrict__ bb,
            const float* __restrict__ W1, const float* __restrict__ al1, const float* __restrict__ ar1,
            const float* __restrict__ W2, const float* __restrict__ al2, const float* __restrict__ ar2){
    if (blockIdx.x < SCAT_BLKS){
        int e = blockIdx.x * 256 + threadIdx.x;
        if (e < Ee){
            int d = dst1[e];
            int p = atomicAdd(&g_slot[0][d], 1);
            if (p < ELLCAP) g_ell[0][d*ELLCAP + p] = src1[e] * 3072;
        } else if (e < 2*Ee){
            int d = dst2[e-Ee];
            int p = atomicAdd(&g_slot[1][d], 1);
            if (p < ELLCAP) g_ell[1][d*ELLCAP + p] = src2[e-Ee] * 3072;
        }
        return;
    }

    __shared__ __align__(16) float sh[64*52];    // raw x, [d][row] stride 52
    __shared__ __align__(16) float sW[64*64];    // [k][c]
    __shared__ __align__(16) float zred[64*52];  // [c][row] stride 52
    __shared__ float red[8];
    __shared__ float nsc[4], nsh[4];
    __shared__ float csum[2][64];

    int tid  = threadIdx.x;
    int lane = tid & 31;
    int w    = tid >> 5;
    int rgrp = w & 3;          // row group (node) of this warp
    int khalf= w >> 2;
    int r0   = rgrp * 12;
    int c0   = 2 * lane;
    int bz   = blockIdx.x - SCAT_BLKS;
    int nt0  = bz * 48;
    int nd0  = bz * 4;
    int dcol = tid & 63;
    int rbas = tid >> 6;

    if (tid < 8) red[tid] = 0.f;
    if (tid >= 128 && tid < 192) csum[0][tid-128] = 0.f;
    if (tid >= 192)              csum[1][tid-192] = 0.f;
    __syncthreads();

    // single-pass staging: raw x -> sh, BN stats from registers
    float ls[4] = {0,0,0,0}, lq[4] = {0,0,0,0};
    #pragma unroll
    for (int it = 0; it < 12; it++){
        float t = x[(size_t)nt0*64 + tid + it*256];
        int row = rbas + it*4;
        sh[dcol*52 + row] = t;
        int nl = row / 12;
        ls[nl] += t; lq[nl] += t*t;
    }
    #pragma unroll
    for (int nl = 0; nl < 4; nl++){
        ls[nl] = radd32(ls[nl]);
        lq[nl] = radd32(lq[nl]);
    }
    if (lane == 0){
        #pragma unroll
        for (int nl = 0; nl < 4; nl++){
            if (ls[nl] != 0.f || lq[nl] != 0.f){
                atomicAdd(&red[2*nl],   ls[nl]);
                atomicAdd(&red[2*nl+1], lq[nl]);
            }
        }
    }
    __syncthreads();
    if (tid < 4){
        float mean = red[2*tid] * (1.f/768.f);
        float var  = red[2*tid+1] * (1.f/768.f) - mean*mean;
        float sc   = rsqrtf(var + 1e-5f) * bg[nd0 + tid];
        nsc[tid] = sc;
        nsh[tid] = bb[nd0 + tid] - mean*sc;
    }
    __syncthreads();

    for (int rel = 0; rel < 2; rel++){
        const float* W  = rel ? W2  : W1;
        const float* al = rel ? al2 : al1;
        const float* ar = rel ? ar2 : ar1;
        for (int i = tid; i < 4096; i += 256) sW[i] = W[i];
        __syncthreads();

        // column sums of W (folded BN shift term)
        {
            float cs = 0.f;
            int q = tid >> 6;
            #pragma unroll
            for (int j = 0; j < 16; j++)
                cs += sW[(q*16 + j)*64 + dcol];
            atomicAdd(&csum[rel][dcol], cs);
        }

        ull acc[2][6];
        #pragma unroll
        for (int c = 0; c < 2; c++)
            #pragma unroll
            for (int i = 0; i < 6; i++) acc[c][i] = 0ull;

        int kb = khalf * 32;
        #pragma unroll 4
        for (int kk = 0; kk < 32; kk++){
            int k = kb + kk;
            ull w2v = *(const ull*)&sW[k*64 + c0];
            float2 wf = upk(w2v);
            ull ws0 = pk(wf.x, wf.x);
            ull ws1 = pk(wf.y, wf.y);
            const float4* hb = (const float4*)&sh[k*52 + r0];
            float4 hA = hb[0], hB = hb[1], hC = hb[2];
            ull h2[6];
            h2[0] = pk(hA.x, hA.y); h2[1] = pk(hA.z, hA.w);
            h2[2] = pk(hB.x, hB.y); h2[3] = pk(hB.z, hB.w);
            h2[4] = pk(hC.x, hC.y); h2[5] = pk(hC.z, hC.w);
            #pragma unroll
            for (int i = 0; i < 6; i++){
                acc[0][i] = fma2(h2[i], ws0, acc[0][i]);
                acc[1][i] = fma2(h2[i], ws1, acc[1][i]);
            }
        }

        if (khalf == 1){
            #pragma unroll
            for (int c = 0; c < 2; c++)
                #pragma unroll
                for (int i = 0; i < 6; i++)
                    *(ull*)&zred[(c0+c)*52 + r0 + 2*i] = acc[c][i];
        }
        __syncthreads();
        if (khalf == 0){
            float scn = nsc[rgrp], shn = nsh[rgrp];
            ull sc2 = pk(scn, scn), sh2v = pk(shn, shn);
            #pragma unroll
            for (int c = 0; c < 2; c++){
                float cv = csum[rel][c0+c];
                ull csv = mul2(pk(cv, cv), sh2v);
                #pragma unroll
                for (int i = 0; i < 6; i++){
                    ull sum = add2(acc[c][i], *(const ull*)&zred[(c0+c)*52 + r0 + 2*i]);
                    acc[c][i] = fma2(sum, sc2, csv);
                }
            }
            #pragma unroll
            for (int c = 0; c < 2; c++)
                #pragma unroll
                for (int i = 0; i < 6; i++)
                    *(ull*)&zred[(c0+c)*52 + r0 + 2*i] = acc[c][i];

            ull al0 = pk(al[c0], al[c0]),   al1v = pk(al[c0+1], al[c0+1]);
            ull ar0 = pk(ar[c0], ar[c0]),   ar1v = pk(ar[c0+1], ar[c0+1]);
            ull pl[6], pr[6];
            #pragma unroll
            for (int i = 0; i < 6; i++){
                pl[i] = fma2(acc[1][i], al1v, mul2(acc[0][i], al0));
                pr[i] = fma2(acc[1][i], ar1v, mul2(acc[0][i], ar0));
            }
            #pragma unroll
            for (int o = 1; o < 8; o <<= 1){
                #pragma unroll
                for (int i = 0; i < 6; i++){
                    pl[i] = add2(pl[i], __shfl_xor_sync(0xffffffffu, pl[i], o));
                    pr[i] = add2(pr[i], __shfl_xor_sync(0xffffffffu, pr[i], o));
                }
            }
            if ((lane & 7) == 0){
                int hd = lane >> 3;
                #pragma unroll
                for (int i = 0; i < 6; i++){
                    float2 fl = upk(pl[i]);
                    float2 fr = upk(pr[i]);
                    int nt = nt0 + r0 + 2*i;
                    g_el[rel][nt*4 + hd]     = fl.x;
                    g_el[rel][(nt+1)*4 + hd] = fl.y;
                    g_er[rel][nt*4 + hd]     = fr.x;
                    g_er[rel][(nt+1)*4 + hd] = fr.y;
                }
            }
        }
        __syncthreads();
        #pragma unroll
        for (int it = 0; it < 12; it++){
            int row = rbas + it*4;
            g_z[rel][(size_t)nt0*64 + tid + it*256] = zred[dcol*52 + row];
        }
        __syncthreads();
    }
}

// ---------------- GAT fallback for deg>32 (cold; noinline to cap regs) -------
struct U2 { ull a, b; };
__device__ __noinline__ U2 gat_fallback(const int* __restrict__ erow, int dg,
                                        int t0, int half, int hA,
                                        const char* elb, const char* zbase,
                                        float4 er0, float4 er1){
    float mx00=-1e30f,mx01=-1e30f,mx02=-1e30f,mx03=-1e30f;
    float mx10=-1e30f,mx11=-1e30f,mx12=-1e30f,mx13=-1e30f;
    int lane = threadIdx.x & 31;
    for (int e = lane; e < dg; e += 32){
        int off = erow[e];
        const char* ep = elb + (off >> 4) + t0*16;
        float4 f0 = *(const float4*)ep;
        float4 f1 = *(const float4*)(ep + 16);
        mx00=fmaxf(mx00, lrelu(f0.x+er0.x)); mx01=fmaxf(mx01, lrelu(f0.y+er0.y));
        mx02=fmaxf(mx02, lrelu(f0.z+er0.z)); mx03=fmaxf(mx03, lrelu(f0.w+er0.w));
        mx10=fmaxf(mx10, lrelu(f1.x+er1.x)); mx11=fmaxf(mx11, lrelu(f1.y+er1.y));
        mx12=fmaxf(mx12, lrelu(f1.z+er1.z)); mx13=fmaxf(mx13, lrelu(f1.w+er1.w));
    }
    mx00=rmax32(mx00); mx01=rmax32(mx01); mx02=rmax32(mx02); mx03=rmax32(mx03);
    mx10=rmax32(mx10); mx11=rmax32(mx11); mx12=rmax32(mx12); mx13=rmax32(mx13);
    float dn00=0.f,dn01=0.f,dn02=0.f,dn03=0.f,dn10=0.f,dn11=0.f,dn12=0.f,dn13=0.f;
    for (int e = lane; e < dg; e += 32){
        int off = erow[e];
        const char* ep = elb + (off >> 4) + t0*16;
        float4 f0 = *(const float4*)ep;
        float4 f1 = *(const float4*)(ep + 16);
        dn00 += __expf(lrelu(f0.x+er0.x)-mx00); dn01 += __expf(lrelu(f0.y+er0.y)-mx01);
        dn02 += __expf(lrelu(f0.z+er0.z)-mx02); dn03 += __expf(lrelu(f0.w+er0.w)-mx03);
        dn10 += __expf(lrelu(f1.x+er1.x)-mx10); dn11 += __expf(lrelu(f1.y+er1.y)-mx11);
        dn12 += __expf(lrelu(f1.z+er1.z)-mx12); dn13 += __expf(lrelu(f1.w+er1.w)-mx13);
    }
    dn00=radd32(dn00); dn01=radd32(dn01); dn02=radd32(dn02); dn03=radd32(dn03);
    dn10=radd32(dn10); dn11=radd32(dn11); dn12=radd32(dn12); dn13=radd32(dn13);

    float dnSel = half ? ((hA==0)?dn10:(hA==1)?dn11:(hA==2)?dn12:dn13)
                       : ((hA==0)?dn00:(hA==1)?dn01:(hA==2)?dn02:dn03);
    float mxSel = half ? ((hA==0)?mx10:(hA==1)?mx11:(hA==2)?mx12:mx13)
                       : ((hA==0)?mx00:(hA==1)?mx01:(hA==2)?mx02:mx03);
    float erSel = half ? ((hA==0)?er1.x:(hA==1)?er1.y:(hA==2)?er1.z:er1.w)
                       : ((hA==0)?er0.x:(hA==1)?er0.y:(hA==2)?er0.z:er0.w);
    float inv = 1.f / fmaxf(dnSel, 1e-16f);

    ull p0=0ull, p1=0ull;
    for (int e = 0; e < dg; ++e){
        int off = erow[e];
        const float* ep = (const float*)(elb + (off >> 4) + (t0+half)*16);
        float a = lrelu(ep[hA] + erSel);
        float wv = __expf(a - mxSel);
        ulonglong2 zA = *(const ulonglong2*)(zbase + off);
        ull w2 = pk(wv, wv);
        p0 = fma2(w2, zA.x, p0);
        p1 = fma2(w2, zA.y, p1);
    }
    ull inv2 = pk(inv, inv);
    U2 r; r.a = mul2(p0, inv2); r.b = mul2(p1, inv2);
    return r;
}

// ---------------- fused GAT (both rels) + residual + BN2 ----------------
__global__ void __launch_bounds__(192, 7) gat_kernel(const float* __restrict__ x,
                           const float* __restrict__ bg, const float* __restrict__ bb){
    __shared__ float s_w[6][32*8];   // [warp][edge*8 + half*4 + head]
    __shared__ float sms[6], sqs[6];

    const unsigned FULL = 0xffffffffu;
    int d    = blockIdx.x;
    int w    = threadIdx.x >> 5;
    int lane = threadIdx.x & 31;
    int half = lane >> 4;
    int l16  = lane & 15;
    int hA   = l16 >> 2;
    int t0   = 2*w;

    // read degrees, then reset counters for next graph replay
    int deg0 = min(g_slot[0][d], ELLCAP);
    int deg1 = min(g_slot[1][d], ELLCAP);
    __syncthreads();
    if (threadIdx.x == 0){ g_slot[0][d] = 0; g_slot[1][d] = 0; }

    ull m01 = 0ull, m23 = 0ull;

    #pragma unroll
    for (int rel = 0; rel < 2; rel++){
        int dg = rel ? deg1 : deg0;
        const int* erow = &g_ell[rel][d*ELLCAP];
        const char* elb   = (const char*)g_el[rel];
        const char* zbase = (const char*)g_z[rel] + (t0+half)*256 + l16*16;
        float4 er0 = *(const float4*)&g_er[rel][d*48 + t0*4];
        float4 er1 = *(const float4*)&g_er[rel][d*48 + t0*4 + 4];

        if (dg <= 32){
            int off = 0;
            float a00=-1e30f,a01=-1e30f,a02=-1e30f,a03=-1e30f;
            float a10=-1e30f,a11=-1e30f,a12=-1e30f,a13=-1e30f;
            if (lane < dg){
                off = erow[lane];
                const char* ep = elb + (off >> 4) + t0*16;
                float4 f0 = *(const float4*)ep;
                float4 f1 = *(const float4*)(ep + 16);
                a00 = lrelu(f0.x + er0.x); a01 = lrelu(f0.y + er0.y);
                a02 = lrelu(f0.z + er0.z); a03 = lrelu(f0.w + er0.w);
                a10 = lrelu(f1.x + er1.x); a11 = lrelu(f1.y + er1.y);
                a12 = lrelu(f1.z + er1.z); a13 = lrelu(f1.w + er1.w);
            }
            float mx00=rmax32(a00), mx01=rmax32(a01), mx02=rmax32(a02), mx03=rmax32(a03);
            float mx10=rmax32(a10), mx11=rmax32(a11), mx12=rmax32(a12), mx13=rmax32(a13);
            float w00=0.f,w01=0.f,w02=0.f,w03=0.f,w10=0.f,w11=0.f,w12=0.f,w13=0.f;
            if (lane < dg){
                w00=__expf(a00-mx00); w01=__expf(a01-mx01);
                w02=__expf(a02-mx02); w03=__expf(a03-mx03);
                w10=__expf(a10-mx10); w11=__expf(a11-mx11);
                w12=__expf(a12-mx12); w13=__expf(a13-mx13);
                *(float4*)&s_w[w][lane*8]     = make_float4(w00,w01,w02,w03);
                *(float4*)&s_w[w][lane*8 + 4] = make_float4(w10,w11,w12,w13);
            }
            float dn00=radd32(w00), dn01=radd32(w01), dn02=radd32(w02), dn03=radd32(w03);
            float dn10=radd32(w10), dn11=radd32(w11), dn12=radd32(w12), dn13=radd32(w13);

            float dnSel = half ? ((hA==0)?dn10:(hA==1)?dn11:(hA==2)?dn12:dn13)
                               : ((hA==0)?dn00:(hA==1)?dn01:(hA==2)?dn02:dn03);
            float inv = 1.f / fmaxf(dnSel, 1e-16f);

            __syncwarp();

            ull p0=0ull, p1=0ull, q0=0ull, q1=0ull;
            const float* wrow = &s_w[w][half*4 + hA];
            int e = 0;
            for (; e + 1 < dg; e += 2){
                int ofA = __shfl_sync(FULL, off, e);
                int ofB = __shfl_sync(FULL, off, e+1);
                float wA = wrow[e*8];
                float wB = wrow[e*8 + 8];
                ulonglong2 zA = *(const ulonglong2*)(zbase + ofA);
                ulonglong2 zB = *(const ulonglong2*)(zbase + ofB);
                ull wA2 = pk(wA, wA), wB2 = pk(wB, wB);
                p0 = fma2(wA2, zA.x, p0);
                p1 = fma2(wA2, zA.y, p1);
                q0 = fma2(wB2, zB.x, q0);
                q1 = fma2(wB2, zB.y, q1);
            }
            if (e < dg){
                int ofA = __shfl_sync(FULL, off, e);
                float wA = wrow[e*8];
                ulonglong2 zA = *(const ulonglong2*)(zbase + ofA);
                ull wA2 = pk(wA, wA);
                p0 = fma2(wA2, zA.x, p0);
                p1 = fma2(wA2, zA.y, p1);
            }
            ull inv2 = pk(inv, inv);
            m01 = add2(m01, mul2(add2(p0, q0), inv2));
            m23 = add2(m23, mul2(add2(p1, q1), inv2));
        } else {
            U2 r = gat_fallback(erow, dg, t0, half, hA, elb, zbase, er0, er1);
            m01 = add2(m01, r.a);
            m23 = add2(m23, r.b);
        }
    }

    size_t idxb = (size_t)d*3072 + (t0+half)*256 + l16*16;
    ulonglong2 xv = *(const ulonglong2*)((const char*)x + idxb);
    ull v01 = add2(xv.x, m01);
    ull v23 = add2(xv.y, m23);

    float2 u01 = upk(v01), u23 = upk(v23);
    float s = radd32(u01.x + u01.y + u23.x + u23.y);
    float q = radd32(u01.x*u01.x + u01.y*u01.y + u23.x*u23.x + u23.y*u23.y);
    if (lane == 0){ sms[w] = s; sqs[w] = q; }
    __syncthreads();
    float ts = 0.f, tq = 0.f;
    #pragma unroll
    for (int i = 0; i < 6; i++){ ts += sms[i]; tq += sqs[i]; }
    float mean = ts * (1.f/768.f);
    float var  = tq * (1.f/768.f) - mean*mean;
    float sc   = rsqrtf(var + 1e-5f) * bg[d];
    float sb   = bb[d] - mean*sc;
    ull sc2 = pk(sc, sc), sb2 = pk(sb, sb);

    ulonglong2 xo, ho;
    xo.x = v01; xo.y = v23;
    ho.x = fma2(v01, sc2, sb2);
    ho.y = fma2(v23, sc2, sb2);
    *(ulonglong2*)((char*)g_x2 + idxb) = xo;
    *(ulonglong2*)((char*)g_h  + idxb) = ho;
}

// ---------------- FFN (register-tiled, 512 thr, 128-row tiles) ----------------
#define FF_TILES ((NTc + 127) / 128)   // 938 (last tile has 64 rows)
#define FF_SMEM ((8192 + 8192 + 128 + 64 + 64*132 + 128*132) * 4)
__global__ void ff_kernel(const float* __restrict__ w1, const float* __restrict__ b1,
                          const float* __restrict__ w2, const float* __restrict__ b2,
                          float* __restrict__ out){
    extern __shared__ float sm[];
    float* sW1 = sm;
    float* sW2 = sW1 + 8192;
    float* sB1 = sW2 + 8192;
    float* sB2 = sB1 + 128;
    float* sX  = sB2 + 64;
    float* sG  = sX  + 64*132;

    int tid  = threadIdx.x;
    int w    = tid >> 5;
    int lane = tid & 31;

    for (int i = tid; i < 8192; i += 512) sW1[i] = w1[i];
    for (int i = tid; i < 8192; i += 512) sW2[i] = w2[i];
    if (tid < 128) sB1[tid] = b1[tid];
    else if (tid < 192) sB2[tid-128] = b2[tid-128];
    __syncthreads();

    float b2v0 = sB2[2*lane], b2v1 = sB2[2*lane+1];

    for (int tile = blockIdx.x; tile < FF_TILES; tile += 148){
        size_t base = (size_t)tile * 128 * 64;

        #pragma unroll
        for (int it = 0; it < 16; it++){
            int i = tid + it*512;
            size_t gi = base + i;
            if (gi < (size_t)NTDc){
                int r = i >> 6, k = i & 63;
                sX[k*132 + r] = g_h[gi];
            }
        }
        __syncthreads();

        ull a1[4][4];
        #pragma unroll
        for (int c = 0; c < 4; c++)
            #pragma unroll
            for (int i = 0; i < 4; i++) a1[c][i] = 0ull;

        #pragma unroll 4
        for (int k = 0; k < 64; k++){
            double2 hd0 = *(const double2*)&sX[k*132 + 8*w];
            double2 hd1 = *(const double2*)&sX[k*132 + 8*w + 4];
            ull h01 = __double_as_longlong(hd0.x);
            ull h23 = __double_as_longlong(hd0.y);
            ull h45 = __double_as_longlong(hd1.x);
            ull h67 = __double_as_longlong(hd1.y);
            float4 wv = *(const float4*)&sW1[k*128 + 4*lane];
            ull ws0 = pk(wv.x, wv.x), ws1 = pk(wv.y, wv.y);
            ull ws2 = pk(wv.z, wv.z), ws3 = pk(wv.w, wv.w);
            a1[0][0] = fma2(h01, ws0, a1[0][0]);
            a1[0][1] = fma2(h23, ws0, a1[0][1]);
            a1[0][2] = fma2(h45, ws0, a1[0][2]);
            a1[0][3] = fma2(h67, ws0, a1[0][3]);
            a1[1][0] = fma2(h01, ws1, a1[1][0]);
            a1[1][1] = fma2(h23, ws1, a1[1][1]);
            a1[1][2] = fma2(h45, ws1, a1[1][2]);
            a1[1][3] = fma2(h67, ws1, a1[1][3]);
            a1[2][0] = fma2(h01, ws2, a1[2][0]);
            a1[2][1] = fma2(h23, ws2, a1[2][1]);
            a1[2][2] = fma2(h45, ws2, a1[2][2]);
            a1[2][3] = fma2(h67, ws2, a1[2][3]);
            a1[3][0] = fma2(h01, ws3, a1[3][0]);
            a1[3][1] = fma2(h23, ws3, a1[3][1]);
            a1[3][2] = fma2(h45, ws3, a1[3][2]);
            a1[3][3] = fma2(h67, ws3, a1[3][3]);
        }

        #pragma unroll
        for (int c = 0; c < 4; c++){
            int j = 4*lane + c;
            float bj = sB1[j];
            float g[8];
            #pragma unroll
            for (int i = 0; i < 4; i++){
                float2 f = upk(a1[c][i]);
                float u0 = f.x + bj, u1 = f.y + bj;
                g[2*i]   = 0.5f * u0 * (1.f + erff(u0 * 0.70710678118654752f));
                g[2*i+1] = 0.5f * u1 * (1.f + erff(u1 * 0.70710678118654752f));
            }
            double2 st0, st1;
            st0.x = __longlong_as_double(pk(g[0], g[1]));
            st0.y = __longlong_as_double(pk(g[2], g[3]));
            st1.x = __longlong_as_double(pk(g[4], g[5]));
            st1.y = __longlong_as_double(pk(g[6], g[7]));
            *(double2*)&sG[j*132 + 8*w]     = st0;
            *(double2*)&sG[j*132 + 8*w + 4] = st1;
        }
        __syncthreads();

        ull a2[2][4];
        #pragma unroll
        for (int c = 0; c < 2; c++)
            #pragma unroll
            for (int i = 0; i < 4; i++) a2[c][i] = 0ull;

        #pragma unroll 4
        for (int k = 0; k < 128; k++){
            double2 gd0 = *(const double2*)&sG[k*132 + 8*w];
            double2 gd1 = *(const double2*)&sG[k*132 + 8*w + 4];
            ull g01 = __double_as_longlong(gd0.x);
            ull g23 = __double_as_longlong(gd0.y);
            ull g45 = __double_as_longlong(gd1.x);
            ull g67 = __double_as_longlong(gd1.y);
            ull wv2 = *(const ull*)&sW2[k*64 + 2*lane];
            float2 wf = upk(wv2);
            ull ws0 = pk(wf.x, wf.x), ws1 = pk(wf.y, wf.y);
            a2[0][0] = fma2(g01, ws0, a2[0][0]);
            a2[0][1] = fma2(g23, ws0, a2[0][1]);
            a2[0][2] = fma2(g45, ws0, a2[0][2]);
            a2[0][3] = fma2(g67, ws0, a2[0][3]);
            a2[1][0] = fma2(g01, ws1, a2[1][0]);
            a2[1][1] = fma2(g23, ws1, a2[1][1]);
            a2[1][2] = fma2(g45, ws1, a2[1][2]);
            a2[1][3] = fma2(g67, ws1, a2[1][3]);
        }

        #pragma unroll
        for (int i = 0; i < 4; i++){
            float2 f0 = upk(a2[0][i]);
            float2 f1 = upk(a2[1][i]);
            size_t o = base + (size_t)(8*w + 2*i)*64 + 2*lane;
            if (o < (size_t)NTDc){
                out[o]    = g_x2[o]    + f0.x + b2v0;
                out[o+1]  = g_x2[o+1]  + f1.x + b2v1;
                out[o+64] = g_x2[o+64] + f0.y + b2v0;
                out[o+65] = g_x2[o+65] + f1.y + b2v1;
            }
        }
        __syncthreads();
    }
}

// ---------------- launcher ----------------
extern "C" void kernel_launch(void* const* d_in, const int* in_sizes, int n_in,
                              void* d_out, int out_size){
    const float* x    = (const float*)d_in[0];
    const int*   src1 = (const int*)d_in[1];
    const int*   dst1 = (const int*)d_in[2];
    const int*   src2 = (const int*)d_in[3];
    const int*   dst2 = (const int*)d_in[4];
    const float* W1   = (const float*)d_in[5];
    const float* al1  = (const float*)d_in[6];
    const float* ar1  = (const float*)d_in[7];
    const float* W2   = (const float*)d_in[8];
    const float* al2  = (const float*)d_in[9];
    const float* ar2  = (const float*)d_in[10];
    const float* bn1g = (const float*)d_in[11];
    const float* bn1b = (const float*)d_in[12];
    const float* bn2g = (const float*)d_in[13];
    const float* bn2b = (const float*)d_in[14];
    const float* fw1  = (const float*)d_in[15];
    const float* fb1  = (const float*)d_in[16];
    const float* fw2  = (const float*)d_in[17];
    const float* fb2  = (const float*)d_in[18];
    float* out = (float*)d_out;

    cudaFuncSetAttribute(ff_kernel, cudaFuncAttributeMaxDynamicSharedMemorySize, FF_SMEM);

    scatter_zel<<<SCAT_BLKS + NTc/48, 256>>>(src1, dst1, src2, dst2,
        x, bn1g, bn1b, W1, al1, ar1, W2, al2, ar2);                 // idx 0
    gat_kernel<<<Nn, 192>>>(x, bn2g, bn2b);                         // idx 1
    ff_kernel<<<148, 512, FF_SMEM>>>(fw1, fb1, fw2, fb2, out);      // idx 2
}

// round 15
// speedup vs baseline: 1.0748x; 1.0748x over previous
#include <cuda_runtime.h>
#include <math.h>

#define Nn   10000
#define Tt   12
#define Ee   100000
#define NTc  (Nn*Tt)        // 120000
#define NTDc (NTc*64)       // 7680000
#define SCAT_BLKS 782       // ceil(2*Ee/256)

typedef unsigned long long ull;

// ---------------- scratch ----------------
__device__ float g_h[NTDc];          // BN2 output (input to FFN)
__device__ float g_z[2][NTDc];       // per-relation projected features
__device__ float g_x2[NTDc];         // residual x + m1 + m2
__device__ float g_el[2][NTc*4];
__device__ float g_er[2][NTc*4];
__device__ int   g_cnt[2*(Nn+1)];    // starts zero; scan re-zeros after reading
__device__ int   g_rowptr[2*(Nn+1)];
__device__ int   g_fill[2*Nn];
__device__ int   g_esrc[2][Ee];      // src node BYTE OFFSETS (src*3072)

// ---------------- f32x2 helpers ----------------
__device__ __forceinline__ ull pk(float a, float b){
    ull r;
    asm("mov.b64 %0, {%1, %2};" : "=l"(r) : "r"(__float_as_uint(a)), "r"(__float_as_uint(b)));
    return r;
}
__device__ __forceinline__ ull fma2(ull a, ull b, ull c){
    ull d;
    asm("fma.rn.f32x2 %0, %1, %2, %3;" : "=l"(d) : "l"(a), "l"(b), "l"(c));
    return d;
}
__device__ __forceinline__ ull mul2(ull a, ull b){
    ull d;
    asm("mul.rn.f32x2 %0, %1, %2;" : "=l"(d) : "l"(a), "l"(b));
    return d;
}
__device__ __forceinline__ ull add2(ull a, ull b){
    ull d;
    asm("add.rn.f32x2 %0, %1, %2;" : "=l"(d) : "l"(a), "l"(b));
    return d;
}
__device__ __forceinline__ float2 upk(ull v){
    unsigned lo, hi;
    asm("mov.b64 {%0, %1}, %2;" : "=r"(lo), "=r"(hi) : "l"(v));
    return make_float2(__uint_as_float(lo), __uint_as_float(hi));
}
// warp-wide reductions via shfl butterfly (no fp32 redux on sm_103)
__device__ __forceinline__ float rmax32(float v){
    #pragma unroll
    for (int o = 16; o; o >>= 1)
        v = fmaxf(v, __shfl_xor_sync(0xffffffffu, v, o));
    return v;
}
__device__ __forceinline__ float radd32(float v){
    #pragma unroll
    for (int o = 16; o; o >>= 1)
        v += __shfl_xor_sync(0xffffffffu, v, o);
    return v;
}
__device__ __forceinline__ float lrelu(float a){
    return (a > 0.f) ? a : 0.2f*a;
}

// ---------------- CSR: histogram ----------------
__global__ void csr_hist(const int* __restrict__ dst1, const int* __restrict__ dst2){
    int e = blockIdx.x * 256 + threadIdx.x;
    if (e < Ee)            atomicAdd(&g_cnt[dst1[e] + 1], 1);
    else if (e < 2*Ee)     atomicAdd(&g_cnt[(Nn+1) + dst2[e-Ee] + 1], 1);
}

// ---------------- CSR: scan (self-zeros g_cnt for next replay) ----------------
__global__ void csr_scan(){
    __shared__ int wsum[32];
    int tid = threadIdx.x, lane = tid & 31, w = tid >> 5;
    for (int rel = 0; rel < 2; rel++){
        int* cnt = g_cnt    + rel*(Nn+1);
        int* rp  = g_rowptr + rel*(Nn+1);
        int* fl  = g_fill   + rel*Nn;
        int base = tid * 10;
        int v[10]; int s = 0;
        #pragma unroll
        for (int i = 0; i < 10; i++){
            int idx = base + i;
            int c = 0;
            if (idx <= Nn){ c = cnt[idx]; cnt[idx] = 0; }
            s += c; v[i] = s;
        }
        int t = s;
        #pragma unroll
        for (int o = 1; o < 32; o <<= 1){
            int u = __shfl_up_sync(0xffffffffu, t, o);
            if (lane >= o) t += u;
        }
        if (lane == 31) wsum[w] = t;
        __syncthreads();
        if (w == 0){
            int ws = wsum[lane];
            #pragma unroll
            for (int o = 1; o < 32; o <<= 1){
                int u = __shfl_up_sync(0xffffffffu, ws, o);
                if (lane >= o) ws += u;
            }
            wsum[lane] = ws;
        }
        __syncthreads();
        int off = ((w > 0) ? wsum[w-1] : 0) + (t - s);
        #pragma unroll
        for (int i = 0; i < 10; i++){
            int idx = base + i;
            if (idx <= Nn){
                int val = off + v[i];
                rp[idx] = val;
                if (idx < Nn) fl[idx] = val;
            }
        }
        __syncthreads();
    }
}

// ---------------- fused: CSR scatter (blocks 0..781) + BN1/z/el/er (rest) -----
// BN1 folded: z = sc_node*(x@W) + shift_node*colsum(W).
__global__ void __launch_bounds__(256, 4)
scatter_zel(const int* __restrict__ src1, const int* __restrict__ dst1,
            const int* __restrict__ src2, const int* __restrict__ dst2,
            const float* __restrict__ x,
            const float* __restrict__ bg, const float* __restrict__ bb,
            const float* __restrict__ W1, const float* __restrict__ al1, const float* __restrict__ ar1,
            const float* __restrict__ W2, const float* __restrict__ al2, const float* __restrict__ ar2){
    if (blockIdx.x < SCAT_BLKS){
        int e = blockIdx.x * 256 + threadIdx.x;
        if (e < Ee){
            int p = atomicAdd(&g_fill[dst1[e]], 1);
            g_esrc[0][p] = src1[e] * 3072;       // z-row byte offset
        } else if (e < 2*Ee){
            int p = atomicAdd(&g_fill[Nn + dst2[e-Ee]], 1);
            g_esrc[1][p] = src2[e-Ee] * 3072;
        }
        return;
    }

    __shared__ __align__(16) float sh[64*52];
    __shared__ __align__(16) float sW[64*64];
    __shared__ __align__(16) float zred[64*52];
    __shared__ float red[8];
    __shared__ float nsc[4], nsh[4];
    __shared__ float csum[2][64];

    int tid  = threadIdx.x;
    int lane = tid & 31;
    int w    = tid >> 5;
    int rgrp = w & 3;
    int khalf= w >> 2;
    int r0   = rgrp * 12;
    int c0   = 2 * lane;
    int bz   = blockIdx.x - SCAT_BLKS;
    int nt0  = bz * 48;
    int nd0  = bz * 4;
    int dcol = tid & 63;
    int rbas = tid >> 6;

    if (tid < 8) red[tid] = 0.f;
    if (tid >= 128 && tid < 192) csum[0][tid-128] = 0.f;
    if (tid >= 192)              csum[1][tid-192] = 0.f;
    __syncthreads();

    float ls[4] = {0,0,0,0}, lq[4] = {0,0,0,0};
    #pragma unroll
    for (int it = 0; it < 12; it++){
        float t = x[(size_t)nt0*64 + tid + it*256];
        int row = rbas + it*4;
        sh[dcol*52 + row] = t;
        int nl = row / 12;
        ls[nl] += t; lq[nl] += t*t;
    }
    #pragma unroll
    for (int nl = 0; nl < 4; nl++){
        ls[nl] = radd32(ls[nl]);
        lq[nl] = radd32(lq[nl]);
    }
    if (lane == 0){
        #pragma unroll
        for (int nl = 0; nl < 4; nl++){
            if (ls[nl] != 0.f || lq[nl] != 0.f){
                atomicAdd(&red[2*nl],   ls[nl]);
                atomicAdd(&red[2*nl+1], lq[nl]);
            }
        }
    }
    __syncthreads();
    if (tid < 4){
        float mean = red[2*tid] * (1.f/768.f);
        float var  = red[2*tid+1] * (1.f/768.f) - mean*mean;
        float sc   = rsqrtf(var + 1e-5f) * bg[nd0 + tid];
        nsc[tid] = sc;
        nsh[tid] = bb[nd0 + tid] - mean*sc;
    }
    __syncthreads();

    for (int rel = 0; rel < 2; rel++){
        const float* W  = rel ? W2  : W1;
        const float* al = rel ? al2 : al1;
        const float* ar = rel ? ar2 : ar1;
        for (int i = tid; i < 4096; i += 256) sW[i] = W[i];
        __syncthreads();

        {
            float cs = 0.f;
            int q = tid >> 6;
            #pragma unroll
            for (int j = 0; j < 16; j++)
                cs += sW[(q*16 + j)*64 + dcol];
            atomicAdd(&csum[rel][dcol], cs);
        }

        ull acc[2][6];
        #pragma unroll
        for (int c = 0; c < 2; c++)
            #pragma unroll
            for (int i = 0; i < 6; i++) acc[c][i] = 0ull;

        int kb = khalf * 32;
        #pragma unroll 4
        for (int kk = 0; kk < 32; kk++){
            int k = kb + kk;
            ull w2v = *(const ull*)&sW[k*64 + c0];
            float2 wf = upk(w2v);
            ull ws0 = pk(wf.x, wf.x);
            ull ws1 = pk(wf.y, wf.y);
            const float4* hb = (const float4*)&sh[k*52 + r0];
            float4 hA = hb[0], hB = hb[1], hC = hb[2];
            ull h2[6];
            h2[0] = pk(hA.x, hA.y); h2[1] = pk(hA.z, hA.w);
            h2[2] = pk(hB.x, hB.y); h2[3] = pk(hB.z, hB.w);
            h2[4] = pk(hC.x, hC.y); h2[5] = pk(hC.z, hC.w);
            #pragma unroll
            for (int i = 0; i < 6; i++){
                acc[0][i] = fma2(h2[i], ws0, acc[0][i]);
                acc[1][i] = fma2(h2[i], ws1, acc[1][i]);
            }
        }

        if (khalf == 1){
            #pragma unroll
            for (int c = 0; c < 2; c++)
                #pragma unroll
                for (int i = 0; i < 6; i++)
                    *(ull*)&zred[(c0+c)*52 + r0 + 2*i] = acc[c][i];
        }
        __syncthreads();
        if (khalf == 0){
            float scn = nsc[rgrp], shn = nsh[rgrp];
            ull sc2 = pk(scn, scn), sh2v = pk(shn, shn);
            #pragma unroll
            for (int c = 0; c < 2; c++){
                float cv = csum[rel][c0+c];
                ull csv = mul2(pk(cv, cv), sh2v);
                #pragma unroll
                for (int i = 0; i < 6; i++){
                    ull sum = add2(acc[c][i], *(const ull*)&zred[(c0+c)*52 + r0 + 2*i]);
                    acc[c][i] = fma2(sum, sc2, csv);
                }
            }
            #pragma unroll
            for (int c = 0; c < 2; c++)
                #pragma unroll
                for (int i = 0; i < 6; i++)
                    *(ull*)&zred[(c0+c)*52 + r0 + 2*i] = acc[c][i];

            ull al0 = pk(al[c0], al[c0]),   al1v = pk(al[c0+1], al[c0+1]);
            ull ar0 = pk(ar[c0], ar[c0]),   ar1v = pk(ar[c0+1], ar[c0+1]);
            ull pl[6], pr[6];
            #pragma unroll
            for (int i = 0; i < 6; i++){
                pl[i] = fma2(acc[1][i], al1v, mul2(acc[0][i], al0));
                pr[i] = fma2(acc[1][i], ar1v, mul2(acc[0][i], ar0));
            }
            #pragma unroll
            for (int o = 1; o < 8; o <<= 1){
                #pragma unroll
                for (int i = 0; i < 6; i++){
                    pl[i] = add2(pl[i], __shfl_xor_sync(0xffffffffu, pl[i], o));
                    pr[i] = add2(pr[i], __shfl_xor_sync(0xffffffffu, pr[i], o));
                }
            }
            if ((lane & 7) == 0){
                int hd = lane >> 3;
                #pragma unroll
                for (int i = 0; i < 6; i++){
                    float2 fl = upk(pl[i]);
                    float2 fr = upk(pr[i]);
                    int nt = nt0 + r0 + 2*i;
                    g_el[rel][nt*4 + hd]     = fl.x;
                    g_el[rel][(nt+1)*4 + hd] = fl.y;
                    g_er[rel][nt*4 + hd]     = fr.x;
                    g_er[rel][(nt+1)*4 + hd] = fr.y;
                }
            }
        }
        __syncthreads();
        #pragma unroll
        for (int it = 0; it < 12; it++){
            int row = rbas + it*4;
            g_z[rel][(size_t)nt0*64 + tid + it*256] = zred[dcol*52 + row];
        }
        __syncthreads();
    }
}

// ---------------- GAT fallback for deg>32 (cold; noinline to cap regs) -------
struct U2 { ull a, b; };
__device__ __noinline__ U2 gat_fallback(const int* __restrict__ esrc, int bg_e, int dg,
                                        int t0, int half, int hA,
                                        const char* elb, const char* zbase,
                                        float4 er0, float4 er1){
    float mx00=-1e30f,mx01=-1e30f,mx02=-1e30f,mx03=-1e30f;
    float mx10=-1e30f,mx11=-1e30f,mx12=-1e30f,mx13=-1e30f;
    int lane = threadIdx.x & 31;
    for (int e = lane; e < dg; e += 32){
        int off = esrc[bg_e + e];
        const char* ep = elb + (off >> 4) + t0*16;
        float4 f0 = *(const float4*)ep;
        float4 f1 = *(const float4*)(ep + 16);
        mx00=fmaxf(mx00, lrelu(f0.x+er0.x)); mx01=fmaxf(mx01, lrelu(f0.y+er0.y));
        mx02=fmaxf(mx02, lrelu(f0.z+er0.z)); mx03=fmaxf(mx03, lrelu(f0.w+er0.w));
        mx10=fmaxf(mx10, lrelu(f1.x+er1.x)); mx11=fmaxf(mx11, lrelu(f1.y+er1.y));
        mx12=fmaxf(mx12, lrelu(f1.z+er1.z)); mx13=fmaxf(mx13, lrelu(f1.w+er1.w));
    }
    mx00=rmax32(mx00); mx01=rmax32(mx01); mx02=rmax32(mx02); mx03=rmax32(mx03);
    mx10=rmax32(mx10); mx11=rmax32(mx11); mx12=rmax32(mx12); mx13=rmax32(mx13);
    float dn00=0.f,dn01=0.f,dn02=0.f,dn03=0.f,dn10=0.f,dn11=0.f,dn12=0.f,dn13=0.f;
    for (int e = lane; e < dg; e += 32){
        int off = esrc[bg_e + e];
        const char* ep = elb + (off >> 4) + t0*16;
        float4 f0 = *(const float4*)ep;
        float4 f1 = *(const float4*)(ep + 16);
        dn00 += __expf(lrelu(f0.x+er0.x)-mx00); dn01 += __expf(lrelu(f0.y+er0.y)-mx01);
        dn02 += __expf(lrelu(f0.z+er0.z)-mx02); dn03 += __expf(lrelu(f0.w+er0.w)-mx03);
        dn10 += __expf(lrelu(f1.x+er1.x)-mx10); dn11 += __expf(lrelu(f1.y+er1.y)-mx11);
        dn12 += __expf(lrelu(f1.z+er1.z)-mx12); dn13 += __expf(lrelu(f1.w+er1.w)-mx13);
    }
    dn00=radd32(dn00); dn01=radd32(dn01); dn02=radd32(dn02); dn03=radd32(dn03);
    dn10=radd32(dn10); dn11=radd32(dn11); dn12=radd32(dn12); dn13=radd32(dn13);

    float dnSel = half ? ((hA==0)?dn10:(hA==1)?dn11:(hA==2)?dn12:dn13)
                       : ((hA==0)?dn00:(hA==1)?dn01:(hA==2)?dn02:dn03);
    float mxSel = half ? ((hA==0)?mx10:(hA==1)?mx11:(hA==2)?mx12:mx13)
                       : ((hA==0)?mx00:(hA==1)?mx01:(hA==2)?mx02:mx03);
    float erSel = half ? ((hA==0)?er1.x:(hA==1)?er1.y:(hA==2)?er1.z:er1.w)
                       : ((hA==0)?er0.x:(hA==1)?er0.y:(hA==2)?er0.z:er0.w);
    float inv = 1.f / fmaxf(dnSel, 1e-16f);

    ull p0=0ull, p1=0ull;
    for (int e = 0; e < dg; ++e){
        int off = esrc[bg_e + e];
        const float* ep = (const float*)(elb + (off >> 4) + (t0+half)*16);
        float a = lrelu(ep[hA] + erSel);
        float wv = __expf(a - mxSel);
        ulonglong2 zA = *(const ulonglong2*)(zbase + off);
        ull w2 = pk(wv, wv);
        p0 = fma2(w2, zA.x, p0);
        p1 = fma2(w2, zA.y, p1);
    }
    ull inv2 = pk(inv, inv);
    U2 r; r.a = mul2(p0, inv2); r.b = mul2(p1, inv2);
    return r;
}

// ---------------- fused GAT (both rels) + residual + BN2 ----------------
__global__ void __launch_bounds__(192, 7) gat_kernel(const float* __restrict__ x,
                           const float* __restrict__ bg, const float* __restrict__ bb){
    __shared__ float s_w[6][32*8];   // [warp][edge*8 + half*4 + head]
    __shared__ float sms[6], sqs[6];

    const unsigned FULL = 0xffffffffu;
    int d    = blockIdx.x;
    int w    = threadIdx.x >> 5;
    int lane = threadIdx.x & 31;
    int half = lane >> 4;
    int l16  = lane & 15;
    int hA   = l16 >> 2;
    int t0   = 2*w;

    ull m01 = 0ull, m23 = 0ull;

    #pragma unroll
    for (int rel = 0; rel < 2; rel++){
        int bg_e = g_rowptr[rel*(Nn+1) + d];
        int dg   = g_rowptr[rel*(Nn+1) + d + 1] - bg_e;
        const char* elb   = (const char*)g_el[rel];
        const char* zbase = (const char*)g_z[rel] + (t0+half)*256 + l16*16;
        float4 er0 = *(const float4*)&g_er[rel][d*48 + t0*4];
        float4 er1 = *(const float4*)&g_er[rel][d*48 + t0*4 + 4];

        if (dg <= 32){
            int off = 0;
            float a00=-1e30f,a01=-1e30f,a02=-1e30f,a03=-1e30f;
            float a10=-1e30f,a11=-1e30f,a12=-1e30f,a13=-1e30f;
            if (lane < dg){
                off = g_esrc[rel][bg_e + lane];
                const char* ep = elb + (off >> 4) + t0*16;
                float4 f0 = *(const float4*)ep;
                float4 f1 = *(const float4*)(ep + 16);
                a00 = lrelu(f0.x + er0.x); a01 = lrelu(f0.y + er0.y);
                a02 = lrelu(f0.z + er0.z); a03 = lrelu(f0.w + er0.w);
                a10 = lrelu(f1.x + er1.x); a11 = lrelu(f1.y + er1.y);
                a12 = lrelu(f1.z + er1.z); a13 = lrelu(f1.w + er1.w);
            }
            float mx00=rmax32(a00), mx01=rmax32(a01), mx02=rmax32(a02), mx03=rmax32(a03);
            float mx10=rmax32(a10), mx11=rmax32(a11), mx12=rmax32(a12), mx13=rmax32(a13);
            float w00=0.f,w01=0.f,w02=0.f,w03=0.f,w10=0.f,w11=0.f,w12=0.f,w13=0.f;
            if (lane < dg){
                w00=__expf(a00-mx00); w01=__expf(a01-mx01);
                w02=__expf(a02-mx02); w03=__expf(a03-mx03);
                w10=__expf(a10-mx10); w11=__expf(a11-mx11);
                w12=__expf(a12-mx12); w13=__expf(a13-mx13);
                *(float4*)&s_w[w][lane*8]     = make_float4(w00,w01,w02,w03);
                *(float4*)&s_w[w][lane*8 + 4] = make_float4(w10,w11,w12,w13);
            }
            float dn00=radd32(w00), dn01=radd32(w01), dn02=radd32(w02), dn03=radd32(w03);
            float dn10=radd32(w10), dn11=radd32(w11), dn12=radd32(w12), dn13=radd32(w13);

            float dnSel = half ? ((hA==0)?dn10:(hA==1)?dn11:(hA==2)?dn12:dn13)
                               : ((hA==0)?dn00:(hA==1)?dn01:(hA==2)?dn02:dn03);
            float inv = 1.f / fmaxf(dnSel, 1e-16f);

            __syncwarp();

            ull p0=0ull, p1=0ull, q0=0ull, q1=0ull;
            const float* wrow = &s_w[w][half*4 + hA];
            int e = 0;
            for (; e + 1 < dg; e += 2){
                int ofA = __shfl_sync(FULL, off, e);
                int ofB = __shfl_sync(FULL, off, e+1);
                float wA = wrow[e*8];
                float wB = wrow[e*8 + 8];
                ulonglong2 zA = *(const ulonglong2*)(zbase + ofA);
                ulonglong2 zB = *(const ulonglong2*)(zbase + ofB);
                ull wA2 = pk(wA, wA), wB2 = pk(wB, wB);
                p0 = fma2(wA2, zA.x, p0);
                p1 = fma2(wA2, zA.y, p1);
                q0 = fma2(wB2, zB.x, q0);
                q1 = fma2(wB2, zB.y, q1);
            }
            if (e < dg){
                int ofA = __shfl_sync(FULL, off, e);
                float wA = wrow[e*8];
                ulonglong2 zA = *(const ulonglong2*)(zbase + ofA);
                ull wA2 = pk(wA, wA);
                p0 = fma2(wA2, zA.x, p0);
                p1 = fma2(wA2, zA.y, p1);
            }
            ull inv2 = pk(inv, inv);
            m01 = add2(m01, mul2(add2(p0, q0), inv2));
            m23 = add2(m23, mul2(add2(p1, q1), inv2));
        } else {
            U2 r = gat_fallback(g_esrc[rel], bg_e, dg, t0, half, hA, elb, zbase, er0, er1);
            m01 = add2(m01, r.a);
            m23 = add2(m23, r.b);
        }
    }

    size_t idxb = (size_t)d*3072 + (t0+half)*256 + l16*16;
    ulonglong2 xv = *(const ulonglong2*)((const char*)x + idxb);
    ull v01 = add2(xv.x, m01);
    ull v23 = add2(xv.y, m23);

    float2 u01 = upk(v01), u23 = upk(v23);
    float s = radd32(u01.x + u01.y + u23.x + u23.y);
    float q = radd32(u01.x*u01.x + u01.y*u01.y + u23.x*u23.x + u23.y*u23.y);
    if (lane == 0){ sms[w] = s; sqs[w] = q; }
    __syncthreads();
    float ts = 0.f, tq = 0.f;
    #pragma unroll
    for (int i = 0; i < 6; i++){ ts += sms[i]; tq += sqs[i]; }
    float mean = ts * (1.f/768.f);
    float var  = tq * (1.f/768.f) - mean*mean;
    float sc   = rsqrtf(var + 1e-5f) * bg[d];
    float sb   = bb[d] - mean*sc;
    ull sc2 = pk(sc, sc), sb2 = pk(sb, sb);

    ulonglong2 xo, ho;
    xo.x = v01; xo.y = v23;
    ho.x = fma2(v01, sc2, sb2);
    ho.y = fma2(v23, sc2, sb2);
    *(ulonglong2*)((char*)g_x2 + idxb) = xo;
    *(ulonglong2*)((char*)g_h  + idxb) = ho;
}

// ---------------- FFN (256 thr, 64-row tiles, 2 blocks/SM; W2 via L1) --------
#define FF_TILES (NTc / 64)            // 1875
#define FF_SMEM ((8192 + 128 + 64 + 64*68 + 128*68) * 4)   // ~86 KB
__global__ void __launch_bounds__(256, 2)
ff_kernel(const float* __restrict__ w1, const float* __restrict__ b1,
          const float* __restrict__ w2, const float* __restrict__ b2,
          float* __restrict__ out){
    extern __shared__ float sm[];
    float* sW1 = sm;                   // [k][j] 64*128
    float* sB1 = sW1 + 8192;           // 128
    float* sB2 = sB1 + 128;            // 64
    float* sX  = sB2 + 64;             // [k][r] 64*68
    float* sG  = sX  + 64*68;          // [j][r] 128*68

    int tid  = threadIdx.x;
    int w    = tid >> 5;
    int lane = tid & 31;

    for (int i = tid; i < 8192; i += 256) sW1[i] = w1[i];
    if (tid < 128) sB1[tid] = b1[tid];
    else if (tid < 192) sB2[tid-128] = b2[tid-128];
    __syncthreads();

    float b2v0 = sB2[2*lane], b2v1 = sB2[2*lane+1];

    for (int tile = blockIdx.x; tile < FF_TILES; tile += 296){
        size_t base = (size_t)tile * 64 * 64;

        #pragma unroll
        for (int it = 0; it < 16; it++){
            int i = tid + it*256;
            int r = i >> 6, k = i & 63;
            sX[k*68 + r] = g_h[base + i];
        }
        __syncthreads();

        // ---- GEMM1: 64x128, k=64 ----
        ull a1[4][4];
        #pragma unroll
        for (int c = 0; c < 4; c++)
            #pragma unroll
            for (int i = 0; i < 4; i++) a1[c][i] = 0ull;

        #pragma unroll 4
        for (int k = 0; k < 64; k++){
            double2 hd0 = *(const double2*)&sX[k*68 + 8*w];
            double2 hd1 = *(const double2*)&sX[k*68 + 8*w + 4];
            ull h01 = __double_as_longlong(hd0.x);
            ull h23 = __double_as_longlong(hd0.y);
            ull h45 = __double_as_longlong(hd1.x);
            ull h67 = __double_as_longlong(hd1.y);
            float4 wv = *(const float4*)&sW1[k*128 + 4*lane];
            ull ws0 = pk(wv.x, wv.x), ws1 = pk(wv.y, wv.y);
            ull ws2 = pk(wv.z, wv.z), ws3 = pk(wv.w, wv.w);
            a1[0][0] = fma2(h01, ws0, a1[0][0]);
            a1[0][1] = fma2(h23, ws0, a1[0][1]);
            a1[0][2] = fma2(h45, ws0, a1[0][2]);
            a1[0][3] = fma2(h67, ws0, a1[0][3]);
            a1[1][0] = fma2(h01, ws1, a1[1][0]);
            a1[1][1] = fma2(h23, ws1, a1[1][1]);
            a1[1][2] = fma2(h45, ws1, a1[1][2]);
            a1[1][3] = fma2(h67, ws1, a1[1][3]);
            a1[2][0] = fma2(h01, ws2, a1[2][0]);
            a1[2][1] = fma2(h23, ws2, a1[2][1]);
            a1[2][2] = fma2(h45, ws2, a1[2][2]);
            a1[2][3] = fma2(h67, ws2, a1[2][3]);
            a1[3][0] = fma2(h01, ws3, a1[3][0]);
            a1[3][1] = fma2(h23, ws3, a1[3][1]);
            a1[3][2] = fma2(h45, ws3, a1[3][2]);
            a1[3][3] = fma2(h67, ws3, a1[3][3]);
        }

        #pragma unroll
        for (int c = 0; c < 4; c++){
            int j = 4*lane + c;
            float bj = sB1[j];
            float g[8];
            #pragma unroll
            for (int i = 0; i < 4; i++){
                float2 f = upk(a1[c][i]);
                float u0 = f.x + bj, u1 = f.y + bj;
                g[2*i]   = 0.5f * u0 * (1.f + erff(u0 * 0.70710678118654752f));
                g[2*i+1] = 0.5f * u1 * (1.f + erff(u1 * 0.70710678118654752f));
            }
            double2 st0, st1;
            st0.x = __longlong_as_double(pk(g[0], g[1]));
            st0.y = __longlong_as_double(pk(g[2], g[3]));
            st1.x = __longlong_as_double(pk(g[4], g[5]));
            st1.y = __longlong_as_double(pk(g[6], g[7]));
            *(double2*)&sG[j*68 + 8*w]     = st0;
            *(double2*)&sG[j*68 + 8*w + 4] = st1;
        }
        __syncthreads();

        // ---- GEMM2: 64x64, k=128; W2 via L1 (global, 32 KB resident) ----
        ull a2[2][4];
        #pragma unroll
        for (int c = 0; c < 2; c++)
            #pragma unroll
            for (int i = 0; i < 4; i++) a2[c][i] = 0ull;

        #pragma unroll 4
        for (int k = 0; k < 128; k++){
            double2 gd0 = *(const double2*)&sG[k*68 + 8*w];
            double2 gd1 = *(const double2*)&sG[k*68 + 8*w + 4];
            ull g01 = __double_as_longlong(gd0.x);
            ull g23 = __double_as_longlong(gd0.y);
            ull g45 = __double_as_longlong(gd1.x);
            ull g67 = __double_as_longlong(gd1.y);
            ull wv2 = __ldg((const ull*)&w2[k*64 + 2*lane]);
            float2 wf = upk(wv2);
            ull ws0 = pk(wf.x, wf.x), ws1 = pk(wf.y, wf.y);
            a2[0][0] = fma2(g01, ws0, a2[0][0]);
            a2[0][1] = fma2(g23, ws0, a2[0][1]);
            a2[0][2] = fma2(g45, ws0, a2[0][2]);
            a2[0][3] = fma2(g67, ws0, a2[0][3]);
            a2[1][0] = fma2(g01, ws1, a2[1][0]);
            a2[1][1] = fma2(g23, ws1, a2[1][1]);
            a2[1][2] = fma2(g45, ws1, a2[1][2]);
            a2[1][3] = fma2(g67, ws1, a2[1][3]);
        }

        #pragma unroll
        for (int i = 0; i < 4; i++){
            float2 f0 = upk(a2[0][i]);
            float2 f1 = upk(a2[1][i]);
            size_t o = base + (size_t)(8*w + 2*i)*64 + 2*lane;
            out[o]    = g_x2[o]    + f0.x + b2v0;
            out[o+1]  = g_x2[o+1]  + f1.x + b2v1;
            out[o+64] = g_x2[o+64] + f0.y + b2v0;
            out[o+65] = g_x2[o+65] + f1.y + b2v1;
        }
        __syncthreads();
    }
}

// ---------------- launcher ----------------
extern "C" void kernel_launch(void* const* d_in, const int* in_sizes, int n_in,
                              void* d_out, int out_size){
    const float* x    = (const float*)d_in[0];
    const int*   src1 = (const int*)d_in[1];
    const int*   dst1 = (const int*)d_in[2];
    const int*   src2 = (const int*)d_in[3];
    const int*   dst2 = (const int*)d_in[4];
    const float* W1   = (const float*)d_in[5];
    const float* al1  = (const float*)d_in[6];
    const float* ar1  = (const float*)d_in[7];
    const float* W2   = (const float*)d_in[8];
    const float* al2  = (const float*)d_in[9];
    const float* ar2  = (const float*)d_in[10];
    const float* bn1g = (const float*)d_in[11];
    const float* bn1b = (const float*)d_in[12];
    const float* bn2g = (const float*)d_in[13];
    const float* bn2b = (const float*)d_in[14];
    const float* fw1  = (const float*)d_in[15];
    const float* fb1  = (const float*)d_in[16];
    const float* fw2  = (const float*)d_in[17];
    const float* fb2  = (const float*)d_in[18];
    float* out = (float*)d_out;

    cudaFuncSetAttribute(ff_kernel, cudaFuncAttributeMaxDynamicSharedMemorySize, FF_SMEM);

    csr_hist<<<(2*Ee + 255)/256, 256>>>(dst1, dst2);               // idx 0
    csr_scan<<<1, 1024>>>();                                        // idx 1
    scatter_zel<<<SCAT_BLKS + NTc/48, 256>>>(src1, dst1, src2, dst2,
        x, bn1g, bn1b, W1, al1, ar1, W2, al2, ar2);                 // idx 2
    gat_kernel<<<Nn, 192>>>(x, bn2g, bn2b);                         // idx 3
    ff_kernel<<<296, 256, FF_SMEM>>>(fw1, fb1, fw2, fb2, out);      // idx 4
}